// round 6
// baseline (speedup 1.0000x reference)
#include <cuda_runtime.h>
#include <cuda_fp16.h>
#include <cstdint>

#define B_   128
#define T_   256
#define K_   256
#define NB   8
#define NTH  512
#define FS   260      // stsh row stride in floats
#define ESS  264      // es row stride in halves (conflict-free LDS pattern)
#define LOG2E 1.4426950408889634f
#define LN2   0.6931471805599453f

static __device__ __forceinline__ uint32_t packh2(float lo, float hi) {
    __half2 h = __floats2half2_rn(lo, hi);
    return *reinterpret_cast<uint32_t*>(&h);
}
static __device__ __forceinline__ void mma16816(float* d, const uint32_t* a,
                                                uint32_t b0, uint32_t b1) {
    asm volatile(
        "mma.sync.aligned.m16n8k16.row.col.f32.f16.f16.f32 "
        "{%0,%1,%2,%3}, {%4,%5,%6,%7}, {%8,%9}, {%0,%1,%2,%3};"
        : "+f"(d[0]), "+f"(d[1]), "+f"(d[2]), "+f"(d[3])
        : "r"(a[0]), "r"(a[1]), "r"(a[2]), "r"(a[3]), "r"(b0), "r"(b1));
}

__global__ __launch_bounds__(NTH, 1)
void crf_loss_kernel(const float* __restrict__ feats,   // [B,T,K]
                     const float* __restrict__ trans,   // [K,K]
                     const int*   __restrict__ tags,    // [B,T]
                     const int*   __restrict__ lens,    // [B]
                     float*       __restrict__ out)     // [B]
{
    __shared__ __align__(16) uint16_t es_s[2][NB * ESS];   // scaled exp(state), fp16, [n][k]
    __shared__ __align__(16) float    stsh[NB * FS];       // final log states
    __shared__ int gsh[2][NB];

    const int tid  = threadIdx.x;
    const int lane = tid & 31;
    const int w    = tid >> 5;        // 16 warps, warp w -> rows [16w,16w+16)
    const int g    = lane >> 2;       // B col n / A row-in-group
    const int tg   = lane & 3;
    const int r0   = w * 16 + g;      // my rows: r0, r0+8
    const int c0   = 2 * tg;          // my batch cols: c0, c0+1
    const int c1   = c0 + 1;
    const int blk  = blockIdx.x;

    // ---- lens ----
    int len0 = 1, len1 = 1, maxlen = 1;
    #pragma unroll
    for (int j = 0; j < NB; ++j) {
        int l = __ldg(lens + blk * NB + j);
        if (j == c0) len0 = l;
        if (j == c1) len1 = l;
        maxlen = max(maxlen, l);
    }

    // per-thread emission pointers (4 scattered streams, L2-resident)
    const float* fp00 = feats + (size_t)(blk * NB + c0) * T_ * K_ + r0;        // (c0, r0)
    const float* fp01 = feats + (size_t)(blk * NB + c1) * T_ * K_ + r0;        // (c1, r0)
    const float* fp10 = fp00 + 8;                                               // (c0, r0+8)
    const float* fp11 = fp01 + 8;                                               // (c1, r0+8)

    // ---- A fragments in registers: A[r][k] = exp(trans[k][r]) as fp16 ----
    uint32_t A[16][4];
    #pragma unroll
    for (int kt = 0; kt < 16; ++kt) {
        const int k0 = kt * 16 + tg * 2;
        float e00 = __expf(__ldg(trans + (size_t)k0 * K_ + r0));
        float e01 = __expf(__ldg(trans + (size_t)(k0 + 1) * K_ + r0));
        float e10 = __expf(__ldg(trans + (size_t)k0 * K_ + r0 + 8));
        float e11 = __expf(__ldg(trans + (size_t)(k0 + 1) * K_ + r0 + 8));
        float e02 = __expf(__ldg(trans + (size_t)(k0 + 8) * K_ + r0));
        float e03 = __expf(__ldg(trans + (size_t)(k0 + 9) * K_ + r0));
        float e12 = __expf(__ldg(trans + (size_t)(k0 + 8) * K_ + r0 + 8));
        float e13 = __expf(__ldg(trans + (size_t)(k0 + 9) * K_ + r0 + 8));
        A[kt][0] = packh2(e00, e01);
        A[kt][1] = packh2(e10, e11);
        A[kt][2] = packh2(e02, e03);
        A[kt][3] = packh2(e12, e13);
    }

    // ---- init ----
    float f00 = fp00[0], f01 = fp01[0], f10 = fp10[0], f11 = fp11[0];   // f_0
    if (tid < NB)   // g0 from f[bj, 0, 0]
        gsh[0][tid] = __float2int_rd(__ldg(feats + (size_t)(blk * NB + tid) * T_ * K_) * LOG2E) + 14;
    __syncthreads();

    int   G0 = gsh[0][c0], G1 = gsh[0][c1];
    int   C0 = G0, C1 = G1;
    float v0 = exp2f(f00 * LOG2E - (float)G0);
    float v1 = exp2f(f01 * LOG2E - (float)G1);
    float v2 = exp2f(f10 * LOG2E - (float)G0);
    float v3 = exp2f(f11 * LOG2E - (float)G1);
    es_s[0][c0 * ESS + r0]     = __half_as_ushort(__float2half_rn(v0));
    es_s[0][c1 * ESS + r0]     = __half_as_ushort(__float2half_rn(v1));
    es_s[0][c0 * ESS + r0 + 8] = __half_as_ushort(__float2half_rn(v2));
    es_s[0][c1 * ESS + r0 + 8] = __half_as_ushort(__float2half_rn(v3));

    // prefetch f_1 into registers
    float fc00 = 0.f, fc01 = 0.f, fc10 = 0.f, fc11 = 0.f;
    if (maxlen > 1) {
        fc00 = fp00[K_]; fc01 = fp01[K_]; fc10 = fp10[K_]; fc11 = fp11[K_];
    }
    __syncthreads();

    // ---- forward recurrence ----
    for (int t = 1; t < maxlen; ++t) {
        const int p = (t - 1) & 1;
        const int q = t & 1;

        // normalizers first: exp2 runs on MUFU while the MMA chain executes
        const int gp0 = gsh[p][c0], gp1 = gsh[p][c1];
        float ef0 = exp2f(fc00 * LOG2E - (float)gp0);
        float ef1 = exp2f(fc01 * LOG2E - (float)gp1);
        float ef2 = exp2f(fc10 * LOG2E - (float)gp0);
        float ef3 = exp2f(fc11 * LOG2E - (float)gp1);

        // prefetch f_{t+1} (consumed only after next barrier -> latency hidden)
        const size_t off = (size_t)((t + 1 < maxlen) ? (t + 1) : t) * K_;
        float fn00 = fp00[off], fn01 = fp01[off], fn10 = fp10[off], fn11 = fp11[off];

        // matvec: D[256,8] = A * ES, 4-way k-split (chains of 4)
        float a0[4] = {0.f, 0.f, 0.f, 0.f};
        float a1[4] = {0.f, 0.f, 0.f, 0.f};
        float a2[4] = {0.f, 0.f, 0.f, 0.f};
        float a3[4] = {0.f, 0.f, 0.f, 0.f};
        const uint16_t* esp = &es_s[p][g * ESS];
        #pragma unroll
        for (int kt = 0; kt < 16; ++kt) {
            uint32_t b0 = *reinterpret_cast<const uint32_t*>(esp + kt * 16 + tg * 2);
            uint32_t b1 = *reinterpret_cast<const uint32_t*>(esp + kt * 16 + tg * 2 + 8);
            float* acc = (kt & 2) ? ((kt & 1) ? a3 : a2) : ((kt & 1) ? a1 : a0);
            mma16816(acc, A[kt], b0, b1);
        }
        float d0 = (a0[0] + a1[0]) + (a2[0] + a3[0]);
        float d1 = (a0[1] + a1[1]) + (a2[1] + a3[1]);
        float d2 = (a0[2] + a1[2]) + (a2[2] + a3[2]);
        float d3 = (a0[3] + a1[3]) + (a2[3] + a3[3]);

        if (t < len0) { v0 = d0 * ef0; v2 = d2 * ef2; C0 += gp0; }
        if (t < len1) { v1 = d1 * ef1; v3 = d3 * ef3; C1 += gp1; }

        if (tid < 4) {   // r0 == 0 owners publish next normalizers
            gsh[q][c0] = ((__float_as_int(v0) >> 23) & 255) - 113;
            gsh[q][c1] = ((__float_as_int(v1) >> 23) & 255) - 113;
        }
        es_s[q][c0 * ESS + r0]     = __half_as_ushort(__float2half_rn(v0));
        es_s[q][c1 * ESS + r0]     = __half_as_ushort(__float2half_rn(v1));
        es_s[q][c0 * ESS + r0 + 8] = __half_as_ushort(__float2half_rn(v2));
        es_s[q][c1 * ESS + r0 + 8] = __half_as_ushort(__float2half_rn(v3));

        fc00 = fn00; fc01 = fn01; fc10 = fn10; fc11 = fn11;
        __syncthreads();
    }

    // ---- final log-domain states ----
    stsh[c0 * FS + r0]     = (log2f(v0) + (float)C0) * LN2;
    stsh[c1 * FS + r0]     = (log2f(v1) + (float)C1) * LN2;
    stsh[c0 * FS + r0 + 8] = (log2f(v2) + (float)C0) * LN2;
    stsh[c1 * FS + r0 + 8] = (log2f(v3) + (float)C1) * LN2;
    __syncthreads();

    // ---- per-batch epilogue: warp w < 8 handles batch j = w ----
    if (w < NB) {
        const int j  = w;
        const int bg = blk * NB + j;
        const int lb = __ldg(lens + bg);

        float sv[8];
        #pragma unroll
        for (int i = 0; i < 8; ++i) sv[i] = stsh[j * FS + lane + 32 * i];

        float bm = sv[0];
        #pragma unroll
        for (int i = 1; i < 8; ++i) bm = fmaxf(bm, sv[i]);
        #pragma unroll
        for (int o = 16; o > 0; o >>= 1)
            bm = fmaxf(bm, __shfl_xor_sync(0xffffffffu, bm, o));

        float ss = 0.f;
        #pragma unroll
        for (int i = 0; i < 8; ++i) ss += __expf(sv[i] - bm);
        #pragma unroll
        for (int o = 16; o > 0; o >>= 1)
            ss += __shfl_xor_sync(0xffffffffu, ss, o);
        float forward = bm + __logf(ss);

        float u = 0.f;
        #pragma unroll
        for (int i = 0; i < 8; ++i) {
            int tp = lane + 32 * i;
            if (tp < lb) {
                int tgd = tags[bg * T_ + tp];
                u += feats[(size_t)bg * T_ * K_ + (size_t)tp * K_ + tgd];
                if (tp + 1 < lb) {
                    int tg2 = tags[bg * T_ + tp + 1];
                    u += __ldg(trans + (size_t)tgd * K_ + tg2);
                }
            }
        }
        #pragma unroll
        for (int o = 16; o > 0; o >>= 1)
            u += __shfl_xor_sync(0xffffffffu, u, o);
        if (lane == 0) out[bg] = forward - u;
    }
}

extern "C" void kernel_launch(void* const* d_in, const int* in_sizes, int n_in,
                              void* d_out, int out_size) {
    const float* feats = (const float*)d_in[0];
    const float* trans = (const float*)d_in[1];
    const int*   tags  = (const int*)d_in[2];
    const int*   lens  = (const int*)d_in[3];
    float*       out   = (float*)d_out;

    crf_loss_kernel<<<B_ / NB, NTH>>>(feats, trans, tags, lens, out);
}

// round 7
// speedup vs baseline: 1.1025x; 1.1025x over previous
#include <cuda_runtime.h>
#include <cuda_fp16.h>
#include <cstdint>

#define B_   128
#define T_   256
#define K_   256
#define NB   8
#define NTH  512
#define FS   260      // staged-f row stride (floats): 8tg+g bank pattern, conflict-free
#define LOG2E 1.4426950408889634f
#define LN2   0.6931471805599453f

static __device__ __forceinline__ uint32_t packh2(float lo, float hi) {
    __half2 h = __floats2half2_rn(lo, hi);
    return *reinterpret_cast<uint32_t*>(&h);
}
static __device__ __forceinline__ uint32_t smem_u32(const void* p) {
    uint32_t a;
    asm("{ .reg .u64 t; cvta.to.shared.u64 t, %1; cvt.u32.u64 %0, t; }" : "=r"(a) : "l"(p));
    return a;
}
static __device__ __forceinline__ void mma16816(float* d, const uint32_t* a,
                                                uint32_t b0, uint32_t b1) {
    asm volatile(
        "mma.sync.aligned.m16n8k16.row.col.f32.f16.f16.f32 "
        "{%0,%1,%2,%3}, {%4,%5,%6,%7}, {%8,%9}, {%0,%1,%2,%3};"
        : "+f"(d[0]), "+f"(d[1]), "+f"(d[2]), "+f"(d[3])
        : "r"(a[0]), "r"(a[1]), "r"(a[2]), "r"(a[3]), "r"(b0), "r"(b1));
}
static __device__ __forceinline__ void ldsm4t(uint32_t* r, uint32_t addr) {
    asm volatile(
        "ldmatrix.sync.aligned.m8n8.x4.trans.shared.b16 {%0,%1,%2,%3}, [%4];"
        : "=r"(r[0]), "=r"(r[1]), "=r"(r[2]), "=r"(r[3]) : "r"(addr));
}

__global__ __launch_bounds__(NTH, 1)
void crf_loss_kernel(const float* __restrict__ feats,   // [B,T,K]
                     const float* __restrict__ trans,   // [K,K]
                     const int*   __restrict__ tags,    // [B,T]
                     const int*   __restrict__ lens,    // [B]
                     float*       __restrict__ out)     // [B]
{
    __shared__ __align__(16) uint16_t es2[2][K_ * NB];   // scaled exp(state), fp16, [k][n]
    __shared__ __align__(16) float    fst[2][NB * FS];   // staged emissions [n][k]
    __shared__ __align__(16) float    stsh[NB * FS];     // final log states
    __shared__ int gsh[2][NB];

    const int tid  = threadIdx.x;
    const int lane = tid & 31;
    const int w    = tid >> 5;        // 16 warps, warp w -> rows [16w,16w+16)
    const int g    = lane >> 2;
    const int tg   = lane & 3;
    const int r0   = w * 16 + g;      // my rows: r0, r0+8
    const int c0   = 2 * tg;          // my batch cols: c0, c0+1
    const int c1   = c0 + 1;
    const int blk  = blockIdx.x;

    // ---- lens ----
    int len0 = 1, len1 = 1, maxlen = 1;
    #pragma unroll
    for (int j = 0; j < NB; ++j) {
        int l = __ldg(lens + blk * NB + j);
        if (j == c0) len0 = l;
        if (j == c1) len1 = l;
        maxlen = max(maxlen, l);
    }

    // ---- A fragments in registers: A[r][k] = exp(trans[k][r]) as fp16 ----
    uint32_t A[16][4];
    #pragma unroll
    for (int kt = 0; kt < 16; ++kt) {
        const int k0 = kt * 16 + tg * 2;
        float e00 = __expf(__ldg(trans + (size_t)k0 * K_ + r0));
        float e01 = __expf(__ldg(trans + (size_t)(k0 + 1) * K_ + r0));
        float e10 = __expf(__ldg(trans + (size_t)k0 * K_ + r0 + 8));
        float e11 = __expf(__ldg(trans + (size_t)(k0 + 1) * K_ + r0 + 8));
        float e02 = __expf(__ldg(trans + (size_t)(k0 + 8) * K_ + r0));
        float e03 = __expf(__ldg(trans + (size_t)(k0 + 9) * K_ + r0));
        float e12 = __expf(__ldg(trans + (size_t)(k0 + 8) * K_ + r0 + 8));
        float e13 = __expf(__ldg(trans + (size_t)(k0 + 9) * K_ + r0 + 8));
        A[kt][0] = packh2(e00, e01);
        A[kt][1] = packh2(e10, e11);
        A[kt][2] = packh2(e02, e03);
        A[kt][3] = packh2(e12, e13);
    }

    // ---- emission staging: thread stages 4 floats of batch sn at col sk ----
    const int sn = tid >> 6;
    const int sk = (tid & 63) * 4;
    const float* fsrc = feats + (size_t)(blk * NB + sn) * T_ * K_ + sk;

    // ---- init: stage f0; prefetch f1, f2 ----
    float4 f0v = *reinterpret_cast<const float4*>(fsrc);
    const int o1 = (maxlen > 1) ? 1 : 0;
    const int o2 = (maxlen > 2) ? 2 : o1;
    float4 f1v = *reinterpret_cast<const float4*>(fsrc + (size_t)o1 * K_);
    float4 fw  = *reinterpret_cast<const float4*>(fsrc + (size_t)o2 * K_);
    *reinterpret_cast<float4*>(&fst[0][sn * FS + sk]) = f0v;
    __syncthreads();

    if (tid < NB)
        gsh[0][tid] = __float2int_rd(fst[0][tid * FS] * LOG2E) + 14;
    float fA = fst[0][c0 * FS + r0];
    float fB = fst[0][c1 * FS + r0];
    float fC = fst[0][c0 * FS + r0 + 8];
    float fD = fst[0][c1 * FS + r0 + 8];
    *reinterpret_cast<float4*>(&fst[1][sn * FS + sk]) = f1v;   // f_1
    __syncthreads();

    int   G0 = gsh[0][c0], G1 = gsh[0][c1];
    int   C0 = G0, C1 = G1;
    float v0 = exp2f(fA * LOG2E - (float)G0);
    float v1 = exp2f(fB * LOG2E - (float)G1);
    float v2 = exp2f(fC * LOG2E - (float)G0);
    float v3 = exp2f(fD * LOG2E - (float)G1);
    *reinterpret_cast<uint32_t*>(&es2[0][r0 * NB + c0])       = packh2(v0, v1);
    *reinterpret_cast<uint32_t*>(&es2[0][(r0 + 8) * NB + c0]) = packh2(v2, v3);
    __syncthreads();

    const uint32_t esb = smem_u32(&es2[0][0]);
    const uint32_t lofs = (uint32_t)lane * 16u;

    // ---- forward recurrence: one barrier per step ----
    for (int t = 1; t < maxlen; ++t) {
        const int p = (t - 1) & 1;
        const int q = t & 1;

        // stage f_{t+1} (loaded last step), prefetch f_{t+2}
        *reinterpret_cast<float4*>(&fst[1 - q][sn * FS + sk]) = fw;
        const int tl = (t + 2 < maxlen) ? (t + 2) : (maxlen - 1);
        fw = *reinterpret_cast<const float4*>(fsrc + (size_t)tl * K_);

        const int gp0 = gsh[p][c0], gp1 = gsh[p][c1];
        float ef0 = exp2f(fst[q][c0 * FS + r0]     * LOG2E - (float)gp0);
        float ef1 = exp2f(fst[q][c1 * FS + r0]     * LOG2E - (float)gp1);
        float ef2 = exp2f(fst[q][c0 * FS + r0 + 8] * LOG2E - (float)gp0);
        float ef3 = exp2f(fst[q][c1 * FS + r0 + 8] * LOG2E - (float)gp1);

        // matvec D[256,8] = A * es, B via ldmatrix.trans, 4-way k-split
        float acc0[4] = {0.f, 0.f, 0.f, 0.f};
        float acc1[4] = {0.f, 0.f, 0.f, 0.f};
        float acc2[4] = {0.f, 0.f, 0.f, 0.f};
        float acc3[4] = {0.f, 0.f, 0.f, 0.f};
        const uint32_t eb = esb + (uint32_t)p * (K_ * NB * 2) + lofs;
        #pragma unroll
        for (int i = 0; i < 8; ++i) {
            uint32_t b[4];
            ldsm4t(b, eb + (uint32_t)i * 512u);
            float* aE = (i & 1) ? acc2 : acc0;   // kt = 2i
            float* aO = (i & 1) ? acc3 : acc1;   // kt = 2i+1
            mma16816(aE, A[2 * i],     b[0], b[1]);
            mma16816(aO, A[2 * i + 1], b[2], b[3]);
        }
        float d0 = (acc0[0] + acc1[0]) + (acc2[0] + acc3[0]);
        float d1 = (acc0[1] + acc1[1]) + (acc2[1] + acc3[1]);
        float d2 = (acc0[2] + acc1[2]) + (acc2[2] + acc3[2]);
        float d3 = (acc0[3] + acc1[3]) + (acc2[3] + acc3[3]);

        if (t < len0) { v0 = d0 * ef0; v2 = d2 * ef2; C0 += gp0; }
        if (t < len1) { v1 = d1 * ef1; v3 = d3 * ef3; C1 += gp1; }

        if (w == 0 && g == 0) {        // row-0 owners publish next normalizers
            gsh[q][c0] = ((__float_as_int(v0) >> 23) & 255) - 113;
            gsh[q][c1] = ((__float_as_int(v1) >> 23) & 255) - 113;
        }
        *reinterpret_cast<uint32_t*>(&es2[q][r0 * NB + c0])       = packh2(v0, v1);
        *reinterpret_cast<uint32_t*>(&es2[q][(r0 + 8) * NB + c0]) = packh2(v2, v3);
        __syncthreads();
    }

    // ---- final log-domain states ----
    stsh[c0 * FS + r0]     = (log2f(v0) + (float)C0) * LN2;
    stsh[c1 * FS + r0]     = (log2f(v1) + (float)C1) * LN2;
    stsh[c0 * FS + r0 + 8] = (log2f(v2) + (float)C0) * LN2;
    stsh[c1 * FS + r0 + 8] = (log2f(v3) + (float)C1) * LN2;
    __syncthreads();

    // ---- per-batch epilogue: warp w < 8 handles batch j = w ----
    if (w < NB) {
        const int j  = w;
        const int bg = blk * NB + j;
        const int lb = __ldg(lens + bg);

        float sv[8];
        #pragma unroll
        for (int i = 0; i < 8; ++i) sv[i] = stsh[j * FS + lane + 32 * i];

        float bm = sv[0];
        #pragma unroll
        for (int i = 1; i < 8; ++i) bm = fmaxf(bm, sv[i]);
        #pragma unroll
        for (int o = 16; o > 0; o >>= 1)
            bm = fmaxf(bm, __shfl_xor_sync(0xffffffffu, bm, o));

        float ss = 0.f;
        #pragma unroll
        for (int i = 0; i < 8; ++i) ss += __expf(sv[i] - bm);
        #pragma unroll
        for (int o = 16; o > 0; o >>= 1)
            ss += __shfl_xor_sync(0xffffffffu, ss, o);
        float forward = bm + __logf(ss);

        float u = 0.f;
        #pragma unroll
        for (int i = 0; i < 8; ++i) {
            int tp = lane + 32 * i;
            if (tp < lb) {
                int tgd = tags[bg * T_ + tp];
                u += feats[(size_t)bg * T_ * K_ + (size_t)tp * K_ + tgd];
                if (tp + 1 < lb) {
                    int tg2 = tags[bg * T_ + tp + 1];
                    u += __ldg(trans + (size_t)tgd * K_ + tg2);
                }
            }
        }
        #pragma unroll
        for (int o = 16; o > 0; o >>= 1)
            u += __shfl_xor_sync(0xffffffffu, u, o);
        if (lane == 0) out[bg] = forward - u;
    }
}

extern "C" void kernel_launch(void* const* d_in, const int* in_sizes, int n_in,
                              void* d_out, int out_size) {
    const float* feats = (const float*)d_in[0];
    const float* trans = (const float*)d_in[1];
    const int*   tags  = (const int*)d_in[2];
    const int*   lens  = (const int*)d_in[3];
    float*       out   = (float*)d_out;

    crf_loss_kernel<<<B_ / NB, NTH>>>(feats, trans, tags, lens, out);
}

// round 8
// speedup vs baseline: 1.7324x; 1.5714x over previous
#include <cuda_runtime.h>
#include <cuda_fp16.h>
#include <cstdint>

#define B_   128
#define T_   256
#define K_   256
#define NTH  256
#define LOG2E 1.4426950408889634f
#define LN2   0.6931471805599453f

static __device__ __forceinline__ uint32_t packh2(float lo, float hi) {
    __half2 h = __floats2half2_rn(lo, hi);
    return *reinterpret_cast<uint32_t*>(&h);
}

__global__ __launch_bounds__(NTH, 1)
void crf_loss_kernel(const float* __restrict__ feats,   // [B,T,K]
                     const float* __restrict__ trans,   // [K,K]
                     const int*   __restrict__ tags,    // [B,T]
                     const int*   __restrict__ lens,    // [B]
                     float*       __restrict__ out)     // [B]
{
    __shared__ __align__(16) __half es[2][K_];   // scaled exp(state), fp16
    __shared__ int   gsh[2];                     // double-buffered log2-normalizer
    __shared__ float red[8];

    const int tid  = threadIdx.x;
    const int lane = tid & 31;
    const int w    = tid >> 5;        // 8 warps
    const int to   = tid;             // one full "to" column per thread
    const int b    = blockIdx.x;

    // ---- ET in registers: ET2[c] = (exp tr[2c][to], exp tr[2c+1][to]) ----
    // 128 fp16x2 regs per thread; global reads coalesced over `to`.
    uint32_t ET2[128];
    {
        const float* tp = trans + to;
        #pragma unroll
        for (int c = 0; c < 128; ++c) {
            float e0 = __expf(__ldg(tp + (size_t)(2 * c)     * K_));
            float e1 = __expf(__ldg(tp + (size_t)(2 * c + 1) * K_));
            ET2[c] = packh2(e0, e1);
        }
    }

    const int len = lens[b];
    const float* fb = feats + (size_t)b * T_ * K_;

    // ---- init: v0 = exp2(f0*log2e - g0), C = g0 ----
    float f0 = fb[to];
    if (tid == 0) gsh[0] = __float2int_rd(f0 * LOG2E) + 14;   // tid0's f0 = f[b,0,0]
    __syncthreads();
    int   g0 = gsh[0];
    int   C  = g0;
    float v  = exp2f(f0 * LOG2E - (float)g0);
    es[0][to] = __float2half_rn(v);
    float fcur = (len > 1) ? fb[K_ + to] : 0.f;   // prefetch f_1 (coalesced)
    __syncthreads();

    // ---- forward recurrence: one barrier per step ----
    for (int t = 1; t < len; ++t) {
        const int p = (t - 1) & 1;
        const int q = t & 1;

        const int gp = gsh[p];
        float efv = exp2f(fcur * LOG2E - (float)gp);   // MUFU, overlaps matvec
        C += gp;
        const int tn = (t + 1 < len) ? (t + 1) : t;
        float fnext = fb[(size_t)tn * K_ + to];        // prefetch f_{t+1}

        // full matvec for my column: 256 from-values, 4 fp16x2 acc chains
        __half2 zz = __float2half2_rn(0.f);
        __half2 a0 = zz, a1 = zz, a2 = zz, a3 = zz;
        const uint4* ep = reinterpret_cast<const uint4*>(es[p]);
        #pragma unroll
        for (int i = 0; i < 32; ++i) {
            uint4 qv = ep[i];   // warp-uniform broadcast, 1 wavefront
            a0 = __hfma2(*reinterpret_cast<__half2*>(&ET2[4 * i + 0]),
                         *reinterpret_cast<__half2*>(&qv.x), a0);
            a1 = __hfma2(*reinterpret_cast<__half2*>(&ET2[4 * i + 1]),
                         *reinterpret_cast<__half2*>(&qv.y), a1);
            a2 = __hfma2(*reinterpret_cast<__half2*>(&ET2[4 * i + 2]),
                         *reinterpret_cast<__half2*>(&qv.z), a2);
            a3 = __hfma2(*reinterpret_cast<__half2*>(&ET2[4 * i + 3]),
                         *reinterpret_cast<__half2*>(&qv.w), a3);
        }
        a0 = __hadd2(a0, a1);
        a2 = __hadd2(a2, a3);
        a0 = __hadd2(a0, a2);
        float2 fx = __half22float2(a0);
        float s = fx.x + fx.y;

        v = s * efv;
        es[q][to] = __float2half_rn(v);
        if (tid == 0)
            gsh[q] = ((__float_as_int(v) >> 23) & 255) - 113;
        fcur = fnext;
        __syncthreads();
    }

    // ---- forward_score = logsumexp_{to}(state), state = (log2 v + C) ln2 ----
    float state = (log2f(v) + (float)C) * LN2;

    float x = state;
    #pragma unroll
    for (int o = 16; o > 0; o >>= 1)
        x = fmaxf(x, __shfl_xor_sync(0xffffffffu, x, o));
    if (lane == 0) red[w] = x;
    __syncthreads();
    float bm = red[0];
    #pragma unroll
    for (int i = 1; i < 8; ++i) bm = fmaxf(bm, red[i]);
    __syncthreads();

    float e = __expf(state - bm);
    #pragma unroll
    for (int o = 16; o > 0; o >>= 1)
        e += __shfl_xor_sync(0xffffffffu, e, o);
    if (lane == 0) red[w] = e;
    __syncthreads();
    float ssum = red[0];
    #pragma unroll
    for (int i = 1; i < 8; ++i) ssum += red[i];
    float forward = bm + __logf(ssum);
    __syncthreads();

    // ---- gold path score: thread tid handles timestep tid (T_ == NTH) ----
    float u = 0.f;
    if (tid < len) {
        int tg = tags[b * T_ + tid];
        u = fb[(size_t)tid * K_ + tg];
        if (tid + 1 < len) {
            int tg2 = tags[b * T_ + tid + 1];
            u += __ldg(trans + (size_t)tg * K_ + tg2);
        }
    }
    #pragma unroll
    for (int o = 16; o > 0; o >>= 1)
        u += __shfl_xor_sync(0xffffffffu, u, o);
    if (lane == 0) red[w] = u;
    __syncthreads();
    if (tid == 0) {
        float us = red[0];
        #pragma unroll
        for (int i = 1; i < 8; ++i) us += red[i];
        out[b] = forward - us;
    }
}

extern "C" void kernel_launch(void* const* d_in, const int* in_sizes, int n_in,
                              void* d_out, int out_size) {
    const float* feats = (const float*)d_in[0];
    const float* trans = (const float*)d_in[1];
    const int*   tags  = (const int*)d_in[2];
    const int*   lens  = (const int*)d_in[3];
    float*       out   = (float*)d_out;

    crf_loss_kernel<<<B_, NTH>>>(feats, trans, tags, lens, out);
}